// round 7
// baseline (speedup 1.0000x reference)
#include <cuda_runtime.h>

// SMFNet B=2,N=8192,D=64,DV=64,M=3 — chord mask = diag + superdiag(wrap).
// out = S · V0 ;  V0 = X@Wg + bg ; S = product of three 2-banded chord mats:
//   out[i] = w0 V0[i] + w1 V0[i+1] + w2 V0[i+2] + w3 V0[i+3]   (wrap)
//   w0 = A3 A2_i A1_i
//   w1 = A3 (A2_i C1_i + C2_i A1_{i+1}) + C3 A2_{i+1} A1_{i+1}
//   w2 = A3 C2_i C1_{i+1} + C3 (A2_{i+1} C1_{i+1} + C2_{i+1} A1_{i+2})
//   w3 = C3 C2_{i+1} C1_{i+2}
//   Am_j = X[j]·Wf[m][:,j] + bf[m][j],  Cm_j = X[j]·Wf[m][:,j+1] + bf[m][j+1]
// Warp-specialized: warps 0-5 GEMM V0, warps 6-7 A/C dots — true overlap.

#define Bc   2
#define Nc   8192
#define Dc   64
#define TROWS 16           // output rows per CTA -> 512 CTAs
#define XR    19           // staged rows per batch (TROWS+3)
#define RS    (2*XR)       // 38 row-slots
#define PAD   68           // float4-aligned row stride
#define ACW   20
#define NTHREADS 256

#define OFF_XS  0
#define OFF_VS  (OFF_XS + RS*PAD)
#define OFF_AS  (OFF_VS + RS*PAD)
#define OFF_CS  (OFF_AS + 6*ACW)
#define SMEM_FLOATS (OFF_CS + 6*ACW)
#define SMEM_BYTES  (SMEM_FLOATS * 4)

__device__ __forceinline__ unsigned long long pack2(float x, float y) {
    unsigned long long r;
    asm("mov.b64 %0, {%1, %2};" : "=l"(r) : "f"(x), "f"(y));
    return r;
}
__device__ __forceinline__ void unpack2(unsigned long long v, float& x, float& y) {
    asm("mov.b64 {%0, %1}, %2;" : "=f"(x), "=f"(y) : "l"(v));
}
__device__ __forceinline__ void fma2(unsigned long long& d,
                                     unsigned long long a, unsigned long long b) {
    asm("fma.rn.f32x2 %0, %1, %2, %3;" : "=l"(d) : "l"(a), "l"(b), "l"(d));
}

__global__ __launch_bounds__(NTHREADS, 4)
void smf_fused_kernel(const float* __restrict__ X,
                      const float* __restrict__ Wg,
                      const float* __restrict__ bg,
                      const float* __restrict__ Wf,
                      const float* __restrict__ bf,
                      float* __restrict__ out)
{
    extern __shared__ float sm[];
    float* Xs = sm + OFF_XS;   // [RS][PAD], rs = b*XR + j
    float* Vs = sm + OFF_VS;   // [RS][PAD]
    float* As = sm + OFF_AS;   // [(b*3+m)*ACW + j]
    float* Cs = sm + OFF_CS;

    const int t  = threadIdx.x;
    const int r0 = blockIdx.x * TROWS;

    // ---- Phase A: stage X rows r0..r0+18 (wrap), both batches ----
    {
        const float4* X4 = reinterpret_cast<const float4*>(X);
        #pragma unroll
        for (int idx = t; idx < RS * 16; idx += NTHREADS) {
            int rs = idx >> 4, q = idx & 15;
            int b  = rs >= XR;
            int j  = rs - b * XR;
            int gi = (r0 + j) & (Nc - 1);
            *reinterpret_cast<float4*>(&Xs[rs * PAD + q * 4]) =
                X4[((size_t)b * Nc + gi) * 16 + q];
        }
    }
    __syncthreads();

    if (t < 192) {
        // ---- Warps 0-5: GEMM V0 = X@Wg + bg over all 38 row-slots ----
        // thread: col quad e0 = 4*(t&15); rows rg, rg+12, rg+24, (+36.. for rg<2)
        const int e0 = (t & 15) * 4;
        const int rg = t >> 4;            // 0..11
        const bool hx = (rg < 2);         // rows 36,37
        const int rx = 36 + rg;

        float4 bgq = __ldg(reinterpret_cast<const float4*>(bg + e0));
        unsigned long long b01 = pack2(bgq.x, bgq.y), b23 = pack2(bgq.z, bgq.w);
        unsigned long long a0_01 = b01, a0_23 = b23;
        unsigned long long a1_01 = b01, a1_23 = b23;
        unsigned long long a2_01 = b01, a2_23 = b23;
        unsigned long long a3_01 = b01, a3_23 = b23;

        #pragma unroll 8
        for (int d = 0; d < Dc; d++) {
            ulonglong2 wq = __ldg(reinterpret_cast<const ulonglong2*>(Wg + d * 64 + e0));
            float x0 = Xs[ rg       * PAD + d];
            float x1 = Xs[(rg + 12) * PAD + d];
            float x2 = Xs[(rg + 24) * PAD + d];
            unsigned long long xx0 = pack2(x0, x0);
            unsigned long long xx1 = pack2(x1, x1);
            unsigned long long xx2 = pack2(x2, x2);
            fma2(a0_01, xx0, wq.x);  fma2(a0_23, xx0, wq.y);
            fma2(a1_01, xx1, wq.x);  fma2(a1_23, xx1, wq.y);
            fma2(a2_01, xx2, wq.x);  fma2(a2_23, xx2, wq.y);
            if (hx) {
                float x3 = Xs[rx * PAD + d];
                unsigned long long xx3 = pack2(x3, x3);
                fma2(a3_01, xx3, wq.x);  fma2(a3_23, xx3, wq.y);
            }
        }
        float v0, v1, v2, v3;
        unpack2(a0_01, v0, v1); unpack2(a0_23, v2, v3);
        *reinterpret_cast<float4*>(&Vs[ rg       * PAD + e0]) = make_float4(v0, v1, v2, v3);
        unpack2(a1_01, v0, v1); unpack2(a1_23, v2, v3);
        *reinterpret_cast<float4*>(&Vs[(rg + 12) * PAD + e0]) = make_float4(v0, v1, v2, v3);
        unpack2(a2_01, v0, v1); unpack2(a2_23, v2, v3);
        *reinterpret_cast<float4*>(&Vs[(rg + 24) * PAD + e0]) = make_float4(v0, v1, v2, v3);
        if (hx) {
            unpack2(a3_01, v0, v1); unpack2(a3_23, v2, v3);
            *reinterpret_cast<float4*>(&Vs[rx * PAD + e0]) = make_float4(v0, v1, v2, v3);
        }
    } else {
        // ---- Warps 6-7: A/C dots, 216 tasks / 64 threads, 4-way interleave ----
        const int t2 = t - 192;
        const float* wp[4];
        int xoff[4];
        float acc[4];
        #pragma unroll
        for (int k = 0; k < 4; k++) {
            int task = t2 + 64 * k;
            int tv = (task < 216) ? task : t2;
            int j = tv % 18;
            int g = tv / 18;
            int isC = g & 1;
            int m   = (g >> 1) % 3;
            int b   = g / 6;
            int gic = (r0 + j + isC) & (Nc - 1);
            wp[k]   = Wf + (size_t)m * Dc * Nc + gic;
            xoff[k] = (b * XR + j) * PAD;
            acc[k]  = 0.f;
        }
        #pragma unroll 8
        for (int d = 0; d < Dc; d++) {
            #pragma unroll
            for (int k = 0; k < 4; k++)
                acc[k] = fmaf(Xs[xoff[k] + d], __ldg(wp[k] + (size_t)d * Nc), acc[k]);
        }
        #pragma unroll
        for (int k = 0; k < 4; k++) {
            int task = t2 + 64 * k;
            if (task < 216) {
                int j = task % 18;
                int g = task / 18;
                int isC = g & 1;
                int m   = (g >> 1) % 3;
                int b   = g / 6;
                int gic = (r0 + j + isC) & (Nc - 1);
                float v = acc[k] + __ldg(bf + m * Nc + gic);
                (isC ? Cs : As)[(b * 3 + m) * ACW + j] = v;
            }
        }
    }
    __syncthreads();

    // ---- Phase C: inline weights + 4-tap combine + store (all threads) ----
    {
        const int e0 = (t & 15) * 4;
        const int jr = t >> 4;
        #pragma unroll
        for (int b = 0; b < Bc; b++) {
            const float* A1 = &As[(b * 3 + 0) * ACW];
            const float* C1 = &Cs[(b * 3 + 0) * ACW];
            const float* A2 = &As[(b * 3 + 1) * ACW];
            const float* C2 = &Cs[(b * 3 + 1) * ACW];
            const float* A3p = &As[(b * 3 + 2) * ACW];
            const float* C3p = &Cs[(b * 3 + 2) * ACW];
            float A1i = A1[jr], A1i1 = A1[jr + 1], A1i2 = A1[jr + 2];
            float C1i = C1[jr], C1i1 = C1[jr + 1], C1i2 = C1[jr + 2];
            float A2i = A2[jr], A2i1 = A2[jr + 1];
            float C2i = C2[jr], C2i1 = C2[jr + 1];
            float A3  = A3p[jr], C3 = C3p[jr];
            float w0 = A3 * A2i * A1i;
            float w1 = A3 * (A2i * C1i + C2i * A1i1) + C3 * A2i1 * A1i1;
            float w2 = A3 * C2i * C1i1 + C3 * (A2i1 * C1i1 + C2i1 * A1i2);
            float w3 = C3 * C2i1 * C1i2;

            const float* vb = &Vs[(b * XR + jr) * PAD + e0];
            float4 p0 = *reinterpret_cast<const float4*>(vb);
            float4 p1 = *reinterpret_cast<const float4*>(vb + PAD);
            float4 p2 = *reinterpret_cast<const float4*>(vb + 2 * PAD);
            float4 p3 = *reinterpret_cast<const float4*>(vb + 3 * PAD);

            float4 o;
            o.x = w0 * p0.x + w1 * p1.x + w2 * p2.x + w3 * p3.x;
            o.y = w0 * p0.y + w1 * p1.y + w2 * p2.y + w3 * p3.y;
            o.z = w0 * p0.z + w1 * p1.z + w2 * p2.z + w3 * p3.z;
            o.w = w0 * p0.w + w1 * p1.w + w2 * p2.w + w3 * p3.w;

            const int gi = r0 + jr;
            *reinterpret_cast<float4*>(&out[((size_t)b * Nc + gi) * 64 + e0]) = o;
        }
    }
}

extern "C" void kernel_launch(void* const* d_in, const int* in_sizes, int n_in,
                              void* d_out, int out_size)
{
    const float* X  = (const float*)d_in[0];   // (2, 8192, 64)
    const float* Wg = (const float*)d_in[1];   // (64, 64)
    const float* bg = (const float*)d_in[2];   // (64,)
    const float* Wf = (const float*)d_in[3];   // (3, 64, 8192)
    const float* bf = (const float*)d_in[4];   // (3, 8192)
    float* out = (float*)d_out;                // (2, 8192, 64)

    cudaFuncSetAttribute(smf_fused_kernel,
                         cudaFuncAttributeMaxDynamicSharedMemorySize, SMEM_BYTES);

    dim3 grid(Nc / TROWS, 1);                  // 512 CTAs
    smf_fused_kernel<<<grid, NTHREADS, SMEM_BYTES>>>(X, Wg, bg, Wf, bf, out);
}